// round 13
// baseline (speedup 1.0000x reference)
#include <cuda_runtime.h>
#include <math.h>

#define N_ 16384
#define D_ 2048
#define H_ 1024

// fp32(exp(-100)) = 27 * 2^-149 (subnormal), bit pattern 0x0000001B.
#define CLIP_P_BITS 27u

// ---------------- scratch (device globals; no allocation allowed) ----------
__device__ float g_s1[N_];         // prefix-640 sum of squares per x row
__device__ int   g_max640_bits;    // atomicMax of prefix-640 mu norms (>=0)
__device__ int   g_max1024_bits;   // atomicMax of prefix-1024 mu norms (>=0)
__device__ int   g_count;          // k_pre last-block counter (self-resetting)
__device__ int   g_done;           // k_fin last-block counter (self-resetting)
__device__ float g_maxsd2;
__device__ float g_yconst;         // y for a clipped row
__device__ float g_th640;          // row clips if prefix-640 x2 > this
__device__ float g_th1024;         // row clips if prefix-1024 x2 > this
__device__ volatile int g_ready;   // k_pre published flag

// Non-FTZ fp32 ops (immune to any -ftz / fast-math compile flags).
__device__ __forceinline__ float mul_rn(float a, float b) {
    float c; asm("mul.rn.f32 %0, %1, %2;" : "=f"(c) : "f"(a), "f"(b)); return c;
}
__device__ __forceinline__ float add_rn(float a, float b) {
    float c; asm("add.rn.f32 %0, %1, %2;" : "=f"(c) : "f"(a), "f"(b)); return c;
}

// ---------------- K1: prologue (PDL primary) --------------------------------
// 512 blocks x 256 threads; two Mu rows per block, first 1024 columns only.
__global__ void __launch_bounds__(256) k_pre(const float* __restrict__ Mu,
                                             const float* __restrict__ Sd,
                                             const float* __restrict__ W) {
    asm volatile("griddepcontrol.launch_dependents;" ::: "memory");

    __shared__ float sh[256];
    __shared__ float sh2[256];
    const int t = threadIdx.x;
    const int warp = t >> 5;
    const int lane = t & 31;
    const int half = t >> 7;                 // 0 or 1: which of the 2 rows
    const int l    = t & 127;
    const int row  = blockIdx.x * 2 + half;

    // 2 float4 per thread cover Mu[row, 0:1024]
    const float4* r = (const float4*)(Mu + (size_t)row * D_);
    float4 va = r[l];            // cols [4l .. 4l+3]      (0..511)
    float4 vb = r[l + 128];      // cols [512+4l .. ]      (512..1023)
    float sa = va.x * va.x + va.y * va.y + va.z * va.z + va.w * va.w;
    float sb = vb.x * vb.x + vb.y * vb.y + vb.z * vb.z + vb.w * vb.w;
    float sq = sa + sb;
    // prefix-640: all of va plus vb where 512+4l < 640 (l < 32)
    float sq6 = sa + ((l < 32) ? sb : 0.0f);
#pragma unroll
    for (int o = 16; o > 0; o >>= 1) {
        sq  += __shfl_xor_sync(0xFFFFFFFFu, sq, o);
        sq6 += __shfl_xor_sync(0xFFFFFFFFu, sq6, o);
    }
    if (lane == 0) { sh[warp] = sq6; sh2[warp] = sq; }
    __syncthreads();
    if (l == 0) {  // t==0 and t==128: one per row
        float m6 = 0.0f, m10 = 0.0f;
#pragma unroll
        for (int i = 0; i < 4; i++) { m6 += sh[half * 4 + i]; m10 += sh2[half * 4 + i]; }
        atomicMax(&g_max640_bits,  __float_as_int(m6));
        atomicMax(&g_max1024_bits, __float_as_int(m10));
    }
    __syncthreads();

    if (blockIdx.x == 0) {
        // maxsd2 + exact subnormal z over 1024 (4 per thread)
        float msd = 0.0f;
        const float C = __uint_as_float(CLIP_P_BITS);
        float zp = 0.0f;
#pragma unroll
        for (int i = 0; i < 4; i++) {
            float sd = Sd[t + 256 * i];
            msd = fmaxf(msd, sd * sd);
            // exact: products are multiples of 2^-149, |sum| << 2^-126,
            // so fp32 adds are exact and order-independent.
            zp = add_rn(zp, mul_rn(C, W[t + 256 * i]));
        }
        sh[t] = msd;
        sh2[t] = zp;
        __syncthreads();
        for (int o = 128; o > 0; o >>= 1) {
            if (t < o) {
                sh[t] = fmaxf(sh[t], sh[t + o]);
                sh2[t] = add_rn(sh2[t], sh2[t + o]);
            }
            __syncthreads();
        }
        if (t == 0) {
            g_maxsd2 = sh[0];
            float z = sh2[0];
            float tt = mul_rn(2.0f / 3.0f, z);                // subnormal-safe
            float th = (fabsf(tt) < 1e-5f) ? tt : tanhf(tt);  // tanh(x)==x tiny
            g_yconst = mul_rn(1.7159f, th);
        }
        __syncthreads();
    }

    if (t == 0) {
        __threadfence();
        int c = atomicAdd(&g_count, 1);
        if (c == (int)gridDim.x - 1) {   // last block: publish thresholds
            __threadfence();
            // For any coordinate-prefix S: dist(n,h) >= (||x_S||-||mu_h,S||)^2
            // when ||x_S|| > ||mu_h,S||. Row clips for all h if
            //   ||x_S|| > max_h||mu_h,S|| + sqrt(200*maxsd2*1.001 + 4)
            // (margins cover our fp error AND the reference's GEMM rounding).
            float R = sqrtf(200.0f * g_maxsd2 * 1.001f + 4.0f);
            float a6  = sqrtf(__int_as_float(g_max640_bits))  + R;
            float a10 = sqrtf(__int_as_float(g_max1024_bits)) + R;
            g_th640  = a6 * a6;
            g_th1024 = a10 * a10;
            g_max640_bits = 0;      // reset for next graph replay
            g_max1024_bits = 0;
            g_count = 0;
            __threadfence();
            g_ready = 1;            // release for k_fin's safety spin
            __threadfence();
        }
    }
}

// ---------------- K2: pure streaming main (no dependencies!) ----------------
// 2048 blocks x 256 threads; warp per x row. Speculative p fill + prefix-640
// sum to scratch. NO griddepcontrol.wait: blocks retire as soon as stores
// drain, so there is no wave-1 stall waiting for k_pre and no decision logic
// (k_fin makes all decisions). ~22 regs, occ 8.
__global__ void __launch_bounds__(256, 8) k_main(const float* __restrict__ x,
                                                 float* __restrict__ p) {
    asm volatile("griddepcontrol.launch_dependents;" ::: "memory");

    const int warp = threadIdx.x >> 5;
    const int lane = threadIdx.x & 31;
    const int n    = blockIdx.x * 8 + warp;
    const float4* xr = (const float4*)(x + (size_t)n * D_);
    float4* prow = (float4*)(p + (size_t)n * H_);

    // Speculative fill: p[n,:] = exp(-100) (input-independent; rare unproven
    // rows are overwritten later by k_fin). Evict-first: pure stream.
    const float C = __uint_as_float(CLIP_P_BITS);
    const float4 c4 = make_float4(C, C, C, C);
#pragma unroll
    for (int i = 0; i < 8; i++) __stcs(prow + lane + 32 * i, c4);

    // Prefix-640 sum of squares (lower bound on ||x_n||^2: sums of squares
    // are monotone in the index set).
    float s = 0.0f;
#pragma unroll
    for (int i = 0; i < 5; i++) {
        float4 v = xr[lane + 32 * i];
        s += v.x * v.x + v.y * v.y + v.z * v.z + v.w * v.w;
    }
#pragma unroll
    for (int o = 16; o > 0; o >>= 1) s += __shfl_xor_sync(0xFFFFFFFFu, s, o);
    if (lane == 0) g_s1[n] = s;
}

// ---------------- K3: finisher (PDL secondary of k_main) --------------------
// 64 blocks x 256 threads; one row per thread. Waits for k_main (PDL) and
// k_pre (flag; k_pre is dispatched first, has no waits, and is long finished
// by the time k_main's 17us complete -- the spin is a correctness guarantee,
// not a schedule assumption: k_pre CANNOT be blocked by anything).
__global__ void __launch_bounds__(256) k_fin(const float* __restrict__ x,
                                             const float* __restrict__ Mu,
                                             const float* __restrict__ Sd,
                                             const float* __restrict__ W,
                                             float* __restrict__ y,
                                             float* __restrict__ p) {
    // k_main completion + memory visibility (g_s1, p).
    asm volatile("griddepcontrol.wait;" ::: "memory");
    // k_pre publication (practically already done).
    if (threadIdx.x == 0) {
        while (g_ready == 0) __nanosleep(64);
    }
    __syncthreads();
    __threadfence();   // acquire

    const float th6  = g_th640;
    const float th10 = g_th1024;
    const float yc   = g_yconst;
    const int lane = threadIdx.x & 31;
    const int n = blockIdx.x * 256 + threadIdx.x;   // 64*256 = 16384 rows

    float s = g_s1[n];
    bool proven = (s > th6);
    if (proven) y[n] = yc;

    // Escalations (~1.6% of rows), warp-cooperative: each unproven row is
    // processed by the whole warp.
    unsigned m = __ballot_sync(0xFFFFFFFFu, !proven);
    while (m) {
        int r = __ffs(m) - 1;
        m &= m - 1;
        int   row  = __shfl_sync(0xFFFFFFFFu, n, r);
        float s640 = __shfl_sync(0xFFFFFFFFu, s, r);
        const float4* xr = (const float4*)(x + (size_t)row * D_);

        // Stage 2: extend to prefix 1024 (3 float4/lane).
        float s2 = 0.0f;
#pragma unroll
        for (int i = 5; i < 8; i++) {
            float4 w4 = xr[lane + 32 * i];
            s2 += w4.x * w4.x + w4.y * w4.y + w4.z * w4.z + w4.w * w4.w;
        }
#pragma unroll
        for (int o = 16; o > 0; o >>= 1) s2 += __shfl_xor_sync(0xFFFFFFFFu, s2, o);
        float st = s640 + s2;

        if (st > th10) {
            if (lane == 0) y[row] = yc;   // p row already correct
            continue;
        }

        // Stage 3: exact fallback (insurance; ~never for this distribution).
        float s3 = 0.0f;
#pragma unroll 1
        for (int i = 8; i < 16; i++) {
            float4 w4 = xr[lane + 32 * i];
            s3 += w4.x * w4.x + w4.y * w4.y + w4.z * w4.z + w4.w * w4.w;
        }
#pragma unroll
        for (int o = 16; o > 0; o >>= 1) s3 += __shfl_xor_sync(0xFFFFFFFFu, s3, o);
        float x2 = st + s3;   // exact ||x_row||^2

        const float* xs = (const float*)xr;
        float z = 0.0f;
#pragma unroll 1
        for (int h = 0; h < H_; h++) {
            const float* mr = Mu + (size_t)h * D_;
            float dot = 0.0f, m2 = 0.0f;
#pragma unroll 1
            for (int k = lane; k < D_; k += 32) {
                float mv = mr[k];
                dot += xs[k] * mv;
                m2  += mv * mv;
            }
#pragma unroll
            for (int o = 16; o > 0; o >>= 1) {
                dot += __shfl_xor_sync(0xFFFFFFFFu, dot, o);
                m2  += __shfl_xor_sync(0xFFFFFFFFu, m2, o);
            }
            float sd = Sd[h];
            float power = -0.5f * (x2 - 2.0f * dot + m2) / (sd * sd);
            power = fminf(fmaxf(power, -100.0f), 40.0f);
            float pv = expf(power);
            if (lane == (h & 31)) p[(size_t)row * H_ + h] = pv;
            if (lane == 0) z += pv * W[h];
        }
        if (lane == 0) {
            float tt = mul_rn(2.0f / 3.0f, z);
            float th = (fabsf(tt) < 1e-5f) ? tt : tanhf(tt);
            y[row] = mul_rn(1.7159f, th);
        }
    }

    // self-reset for the next graph replay (last block clears the flag;
    // replays are stream-serialized, so no cross-replay race).
    __syncthreads();
    if (threadIdx.x == 0) {
        __threadfence();
        int c = atomicAdd(&g_done, 1);
        if (c == (int)gridDim.x - 1) {
            g_ready = 0;
            g_done = 0;
            __threadfence();
        }
    }
}

extern "C" void kernel_launch(void* const* d_in, const int* in_sizes, int n_in,
                              void* d_out, int out_size) {
    const float* x  = (const float*)d_in[0];
    const float* Mu = (const float*)d_in[1];
    const float* Sd = (const float*)d_in[2];
    const float* W  = (const float*)d_in[3];
    float* y = (float*)d_out;          // first N_ elements
    float* p = (float*)d_out + N_;     // then N_*H_ elements

    k_pre<<<512, 256>>>(Mu, Sd, W);

    cudaLaunchAttribute attrs[1];
    attrs[0].id = cudaLaunchAttributeProgrammaticStreamSerialization;
    attrs[0].val.programmaticStreamSerializationAllowed = 1;

    // k_main: PDL-secondary of k_pre (concurrent, but takes no dependency on
    // its results -- it never waits).
    cudaLaunchConfig_t cfg = {};
    cfg.gridDim  = dim3(2048, 1, 1);
    cfg.blockDim = dim3(256, 1, 1);
    cfg.dynamicSmemBytes = 0;
    cfg.stream = 0;
    cfg.attrs = attrs;
    cfg.numAttrs = 1;
    cudaLaunchKernelEx(&cfg, k_main, x, p);

    // k_fin: PDL-secondary of k_main; waits in-kernel.
    cudaLaunchConfig_t cfg2 = {};
    cfg2.gridDim  = dim3(64, 1, 1);
    cfg2.blockDim = dim3(256, 1, 1);
    cfg2.dynamicSmemBytes = 0;
    cfg2.stream = 0;
    cfg2.attrs = attrs;
    cfg2.numAttrs = 1;
    cudaLaunchKernelEx(&cfg2, k_fin, x, Mu, Sd, W, y, p);
}

// round 14
// speedup vs baseline: 1.0011x; 1.0011x over previous
#include <cuda_runtime.h>
#include <math.h>

#define N_ 16384
#define D_ 2048
#define H_ 1024

// fp32(exp(-100)) = 27 * 2^-149 (subnormal), bit pattern 0x0000001B.
#define CLIP_P_BITS 27u

// ---------------- scratch (device globals; no allocation allowed) ----------
__device__ int   g_max640_bits;    // atomicMax of prefix-640 mu norms (>=0)
__device__ int   g_max1024_bits;   // atomicMax of prefix-1024 mu norms (>=0)
__device__ int   g_count;          // last-block-done counter (self-resetting)
__device__ float g_maxsd2;
__device__ float g_yconst;         // y for a clipped row
__device__ float g_th640;          // row clips if prefix-640 x2 > this
__device__ float g_th1024;         // row clips if prefix-1024 x2 > this

// Non-FTZ fp32 ops (immune to any -ftz / fast-math compile flags).
__device__ __forceinline__ float mul_rn(float a, float b) {
    float c; asm("mul.rn.f32 %0, %1, %2;" : "=f"(c) : "f"(a), "f"(b)); return c;
}
__device__ __forceinline__ float add_rn(float a, float b) {
    float c; asm("add.rn.f32 %0, %1, %2;" : "=f"(c) : "f"(a), "f"(b)); return c;
}

// ---------------- K1: prologue (PDL primary) --------------------------------
// 128 blocks x 256 threads; warp per Mu row (8 rows/block), 8 independent
// float4 loads per lane (MLP=8) covering Mu[row, 0:1024]. R13 profiling
// showed the old MLP=2 layout was latency-bound at ~10us; MLP=8 over 128
// blocks should run the 4MB read near bandwidth (~2us), letting k_main's
// wave-1 blocks clear their griddepcontrol.wait early so wave 2 overlaps.
__global__ void __launch_bounds__(256) k_pre(const float* __restrict__ Mu,
                                             const float* __restrict__ Sd,
                                             const float* __restrict__ W) {
    asm volatile("griddepcontrol.launch_dependents;" ::: "memory");

    __shared__ float sh[256];
    __shared__ float sh2[256];
    const int t = threadIdx.x;
    const int warp = t >> 5;
    const int lane = t & 31;
    const int row  = blockIdx.x * 8 + warp;

    // 8 independent float4 per lane cover Mu[row, 0:1024]
    const float4* r = (const float4*)(Mu + (size_t)row * D_);
    float4 v[8];
#pragma unroll
    for (int j = 0; j < 8; j++) v[j] = r[lane + 32 * j];

    float sq = 0.0f, sq6 = 0.0f;
#pragma unroll
    for (int j = 0; j < 8; j++) {
        float q = v[j].x * v[j].x + v[j].y * v[j].y
                + v[j].z * v[j].z + v[j].w * v[j].w;
        sq += q;
        if (j < 5) sq6 += q;   // float4 idx < 160 <=> cols < 640
    }
#pragma unroll
    for (int o = 16; o > 0; o >>= 1) {
        sq  += __shfl_xor_sync(0xFFFFFFFFu, sq, o);
        sq6 += __shfl_xor_sync(0xFFFFFFFFu, sq6, o);
    }
    if (lane == 0) {
        atomicMax(&g_max640_bits,  __float_as_int(sq6));
        atomicMax(&g_max1024_bits, __float_as_int(sq));
    }

    if (blockIdx.x == 0) {
        // maxsd2 + exact subnormal z over 1024 (4 per thread)
        float msd = 0.0f;
        const float C = __uint_as_float(CLIP_P_BITS);
        float zp = 0.0f;
#pragma unroll
        for (int i = 0; i < 4; i++) {
            float sd = Sd[t + 256 * i];
            msd = fmaxf(msd, sd * sd);
            // exact: products are multiples of 2^-149, |sum| << 2^-126,
            // so fp32 adds are exact and order-independent.
            zp = add_rn(zp, mul_rn(C, W[t + 256 * i]));
        }
        sh[t] = msd;
        sh2[t] = zp;
        __syncthreads();
        for (int o = 128; o > 0; o >>= 1) {
            if (t < o) {
                sh[t] = fmaxf(sh[t], sh[t + o]);
                sh2[t] = add_rn(sh2[t], sh2[t + o]);
            }
            __syncthreads();
        }
        if (t == 0) {
            g_maxsd2 = sh[0];
            float z = sh2[0];
            float tt = mul_rn(2.0f / 3.0f, z);                // subnormal-safe
            float th = (fabsf(tt) < 1e-5f) ? tt : tanhf(tt);  // tanh(x)==x tiny
            g_yconst = mul_rn(1.7159f, th);
        }
    }
    __syncthreads();

    if (t == 0) {
        __threadfence();
        int c = atomicAdd(&g_count, 1);
        if (c == (int)gridDim.x - 1) {   // last block: publish thresholds
            __threadfence();
            // For any coordinate-prefix S: dist(n,h) >= (||x_S||-||mu_h,S||)^2
            // when ||x_S|| > ||mu_h,S||. Row clips for all h if
            //   ||x_S|| > max_h||mu_h,S|| + sqrt(200*maxsd2*1.001 + 4)
            // (margins cover our fp error AND the reference's GEMM rounding).
            float R = sqrtf(200.0f * g_maxsd2 * 1.001f + 4.0f);
            float a6  = sqrtf(__int_as_float(g_max640_bits))  + R;
            float a10 = sqrtf(__int_as_float(g_max1024_bits)) + R;
            g_th640  = a6 * a6;
            g_th1024 = a10 * a10;
            // reset for next graph replay
            g_max640_bits = 0;
            g_max1024_bits = 0;
            g_count = 0;
            __threadfence();
        }
    }
}

// ---------------- K2: fused main (PDL secondary) — R9 verbatim --------------
// 2048 blocks x 256 threads; warp per x row. Stage-1 x loads (prefix 640)
// and the SPECULATIVE p-row fill (input-independent value) issue BEFORE
// griddepcontrol.wait, hiding k_pre under the streaming.
__global__ void __launch_bounds__(256, 5) k_main(const float* __restrict__ x,
                                                 const float* __restrict__ Mu,
                                                 const float* __restrict__ Sd,
                                                 const float* __restrict__ W,
                                                 float* __restrict__ y,
                                                 float* __restrict__ p) {
    const int warp = threadIdx.x >> 5;
    const int lane = threadIdx.x & 31;
    const int n    = blockIdx.x * 8 + warp;
    const float4* xr = (const float4*)(x + (size_t)n * D_);
    float4* prow = (float4*)(p + (size_t)n * H_);

    // Stage 1: lower bound on ||x_n||^2 from the first 640 elems
    // (sums of squares are monotone, so any prefix is a valid lower bound)
    float4 v[5];
#pragma unroll
    for (int i = 0; i < 5; i++) v[i] = xr[lane + 32 * i];

    // Speculative fill: p[n,:] = exp(-100). Correct for ~every row; a rare
    // unproven row is recomputed and overwritten after verification.
    const float C = __uint_as_float(CLIP_P_BITS);
    const float4 c4 = make_float4(C, C, C, C);
#pragma unroll
    for (int i = 0; i < 8; i++) __stcs(prow + lane + 32 * i, c4);

    float s = 0.0f;
#pragma unroll
    for (int i = 0; i < 5; i++)
        s += v[i].x * v[i].x + v[i].y * v[i].y + v[i].z * v[i].z + v[i].w * v[i].w;
#pragma unroll
    for (int o = 16; o > 0; o >>= 1) s += __shfl_xor_sync(0xFFFFFFFFu, s, o);

    // Wait for k_pre completion (+ memory visibility). HW wait, not a spin.
    asm volatile("griddepcontrol.wait;" ::: "memory");

    bool clipped = (s > g_th640);
    if (!clipped) {
        // Stage 2: extend to prefix 1024 (3 more float4/lane; ~5% of rows)
        float s2 = 0.0f;
#pragma unroll
        for (int i = 5; i < 8; i++) {
            float4 w4 = __ldcs(xr + lane + 32 * i);
            s2 += w4.x * w4.x + w4.y * w4.y + w4.z * w4.z + w4.w * w4.w;
        }
#pragma unroll
        for (int o = 16; o > 0; o >>= 1) s2 += __shfl_xor_sync(0xFFFFFFFFu, s2, o);
        s += s2;
        clipped = (s > g_th1024);
    }

    if (clipped) {
        if (lane == 0) y[n] = g_yconst;   // speculative p row already correct
    } else {
        // Stage 3: exact fallback for an unproven row (insurance; ~never).
        // Computes full x2, and mu2 inline per h. Scalar + unroll-1 keeps the
        // cold path from inflating hot-path registers.
        float s3 = 0.0f;
#pragma unroll 1
        for (int i = 8; i < 16; i++) {
            float4 w4 = __ldcs(xr + lane + 32 * i);
            s3 += w4.x * w4.x + w4.y * w4.y + w4.z * w4.z + w4.w * w4.w;
        }
#pragma unroll
        for (int o = 16; o > 0; o >>= 1) s3 += __shfl_xor_sync(0xFFFFFFFFu, s3, o);
        s += s3;   // exact ||x_n||^2

        const float* xs = (const float*)xr;
        float z = 0.0f;
#pragma unroll 1
        for (int h = 0; h < H_; h++) {
            const float* mr = Mu + (size_t)h * D_;
            float dot = 0.0f, m2 = 0.0f;
#pragma unroll 1
            for (int k = lane; k < D_; k += 32) {
                float mv = mr[k];
                dot += xs[k] * mv;
                m2  += mv * mv;
            }
#pragma unroll
            for (int o = 16; o > 0; o >>= 1) {
                dot += __shfl_xor_sync(0xFFFFFFFFu, dot, o);
                m2  += __shfl_xor_sync(0xFFFFFFFFu, m2, o);
            }
            float sd = Sd[h];
            float power = -0.5f * (s - 2.0f * dot + m2) / (sd * sd);
            power = fminf(fmaxf(power, -100.0f), 40.0f);
            float pv = expf(power);
            // Same-lane overwrite of the speculative fill (lane owns h with
            // ((h>>2)&31)==lane) => same-thread program order, no race.
            if (lane == ((h >> 2) & 31)) p[(size_t)n * H_ + h] = pv;
            if (lane == 0) z += pv * W[h];
        }
        if (lane == 0) {
            float tt = mul_rn(2.0f / 3.0f, z);
            float th = (fabsf(tt) < 1e-5f) ? tt : tanhf(tt);
            y[n] = mul_rn(1.7159f, th);
        }
    }
}

extern "C" void kernel_launch(void* const* d_in, const int* in_sizes, int n_in,
                              void* d_out, int out_size) {
    const float* x  = (const float*)d_in[0];
    const float* Mu = (const float*)d_in[1];
    const float* Sd = (const float*)d_in[2];
    const float* W  = (const float*)d_in[3];
    float* y = (float*)d_out;          // first N_ elements
    float* p = (float*)d_out + N_;     // then N_*H_ elements

    k_pre<<<128, 256>>>(Mu, Sd, W);

    // k_main with Programmatic Dependent Launch: it begins executing while
    // k_pre is still running; it synchronizes in-kernel via griddepcontrol.wait.
    cudaLaunchAttribute attrs[1];
    attrs[0].id = cudaLaunchAttributeProgrammaticStreamSerialization;
    attrs[0].val.programmaticStreamSerializationAllowed = 1;

    cudaLaunchConfig_t cfg = {};
    cfg.gridDim  = dim3(2048, 1, 1);
    cfg.blockDim = dim3(256, 1, 1);
    cfg.dynamicSmemBytes = 0;
    cfg.stream = 0;            // legacy default stream (the captured stream)
    cfg.attrs = attrs;
    cfg.numAttrs = 1;

    cudaLaunchKernelEx(&cfg, k_main, x, Mu, Sd, W, y, p);
}

// round 15
// speedup vs baseline: 1.4308x; 1.4292x over previous
#include <cuda_runtime.h>
#include <math.h>

#define N_ 16384
#define D_ 2048
#define H_ 1024

// fp32(exp(-100)) = 27 * 2^-149 (subnormal), bit pattern 0x0000001B.
#define CLIP_P_BITS 27u

// Stage prefixes (elements of each x row): stage-1 = 640 (5 float4/lane),
// stage-2 extends to 1024 (3 more float4/lane), stage-3 = exact fallback.
#define P1 640

// ---------------- scratch (device globals; no allocation allowed) ----------
__device__ int   g_max640_bits;    // atomicMax of prefix-640 mu norms (>=0)
__device__ int   g_max1024_bits;   // atomicMax of prefix-1024 mu norms (>=0)
__device__ int   g_count;          // last-block-done counter (self-resetting)
__device__ float g_maxsd2;
__device__ float g_zconst;         // exact subnormal z for a clipped row
__device__ float g_yconst;         // y for a clipped row
__device__ float g_th640;          // row clips if prefix-640 x2 > this
__device__ float g_th1024;         // row clips if prefix-1024 x2 > this

// Non-FTZ fp32 ops (immune to any -ftz / fast-math compile flags).
__device__ __forceinline__ float mul_rn(float a, float b) {
    float c; asm("mul.rn.f32 %0, %1, %2;" : "=f"(c) : "f"(a), "f"(b)); return c;
}
__device__ __forceinline__ float add_rn(float a, float b) {
    float c; asm("add.rn.f32 %0, %1, %2;" : "=f"(c) : "f"(a), "f"(b)); return c;
}

// ---------------- K1: prologue (PDL primary) --------------------------------
// 1024 blocks x 256 threads; one Mu row per block, but only the first 1024
// columns (4 MB total): the clip thresholds only need PREFIX norms.
__global__ void __launch_bounds__(256) k_pre(const float* __restrict__ Mu,
                                             const float* __restrict__ Sd,
                                             const float* __restrict__ W) {
    // Signal PDL dependents immediately: k_main may launch, stream its x
    // loads AND its speculative p stores while we compute.
    asm volatile("griddepcontrol.launch_dependents;" ::: "memory");

    __shared__ float sh[256];
    __shared__ float sh2[256];
    const int t = threadIdx.x;
    const int warp = t >> 5;
    const int lane = t & 31;
    const int row = blockIdx.x;

    // one float4 per thread covers Mu[row, 0:1024]
    const float4* r = (const float4*)(Mu + (size_t)row * D_);
    float4 v = r[t];
    float sq = v.x * v.x + v.y * v.y + v.z * v.z + v.w * v.w;
    float sq6 = (t < P1 / 4) ? sq : 0.0f;    // first 160 float4 = prefix 640
#pragma unroll
    for (int o = 16; o > 0; o >>= 1) {
        sq  += __shfl_xor_sync(0xFFFFFFFFu, sq, o);
        sq6 += __shfl_xor_sync(0xFFFFFFFFu, sq6, o);
    }
    if (lane == 0) { sh[warp] = sq6; sh2[warp] = sq; }
    __syncthreads();
    if (t == 0) {
        float m6 = 0.0f, m10 = 0.0f;
#pragma unroll
        for (int i = 0; i < 8; i++) { m6 += sh[i]; m10 += sh2[i]; }
        atomicMax(&g_max640_bits,  __float_as_int(m6));
        atomicMax(&g_max1024_bits, __float_as_int(m10));
    }
    __syncthreads();

    if (blockIdx.x == 0) {
        // maxsd2 + exact subnormal z over 1024 (4 per thread)
        float msd = 0.0f;
        const float C = __uint_as_float(CLIP_P_BITS);
        float zp = 0.0f;
#pragma unroll
        for (int i = 0; i < 4; i++) {
            float sd = Sd[t + 256 * i];
            msd = fmaxf(msd, sd * sd);
            // exact: products are multiples of 2^-149, |sum| << 2^-126,
            // so fp32 adds are exact and order-independent.
            zp = add_rn(zp, mul_rn(C, W[t + 256 * i]));
        }
        sh[t] = msd;
        sh2[t] = zp;
        __syncthreads();
        for (int o = 128; o > 0; o >>= 1) {
            if (t < o) {
                sh[t] = fmaxf(sh[t], sh[t + o]);
                sh2[t] = add_rn(sh2[t], sh2[t + o]);
            }
            __syncthreads();
        }
        if (t == 0) {
            g_maxsd2 = sh[0];
            float z = sh2[0];
            g_zconst = z;
            float tt = mul_rn(2.0f / 3.0f, z);                // subnormal-safe
            float th = (fabsf(tt) < 1e-5f) ? tt : tanhf(tt);  // tanh(x)==x tiny
            g_yconst = mul_rn(1.7159f, th);
        }
        __syncthreads();
    }

    if (t == 0) {
        __threadfence();
        int c = atomicAdd(&g_count, 1);
        if (c == (int)gridDim.x - 1) {   // last block: publish thresholds
            __threadfence();
            // For any coordinate-prefix S: dist(n,h) >= (||x_S||-||mu_h,S||)^2
            // when ||x_S|| > ||mu_h,S||. Row clips for all h if
            //   ||x_S|| > max_h||mu_h,S|| + sqrt(200*maxsd2*1.001 + 4)
            // (margins cover our fp error AND the reference's GEMM rounding).
            float R = sqrtf(200.0f * g_maxsd2 * 1.001f + 4.0f);
            float a6  = sqrtf(__int_as_float(g_max640_bits))  + R;
            float a10 = sqrtf(__int_as_float(g_max1024_bits)) + R;
            g_th640  = a6 * a6;
            g_th1024 = a10 * a10;
            // reset for next graph replay
            g_max640_bits = 0;
            g_max1024_bits = 0;
            g_count = 0;
            __threadfence();
        }
    }
}

// ---------------- K2: fused main (PDL secondary) ----------------------------
// 2048 blocks x 256 threads; warp per x row.
// Stage-1 x loads (prefix 640) and the SPECULATIVE p-row fill (value C is
// input-independent) are issued BEFORE griddepcontrol.wait, hiding k_pre.
// Stage-2 (prefix 1024, ~5% of rows) and stage-3 (exact fallback, ~never)
// run after the wait.
__global__ void __launch_bounds__(256, 5) k_main(const float* __restrict__ x,
                                                 const float* __restrict__ Mu,
                                                 const float* __restrict__ Sd,
                                                 const float* __restrict__ W,
                                                 float* __restrict__ y,
                                                 float* __restrict__ p) {
    const int warp = threadIdx.x >> 5;
    const int lane = threadIdx.x & 31;
    const int n    = blockIdx.x * 8 + warp;
    const float4* xr = (const float4*)(x + (size_t)n * D_);
    float4* prow = (float4*)(p + (size_t)n * H_);

    // Stage 1: lower bound on ||x_n||^2 from the first 640 elems
    // (sums of squares are monotone, so any prefix is a valid lower bound)
    float4 v[5];
#pragma unroll
    for (int i = 0; i < 5; i++) v[i] = xr[lane + 32 * i];

    // Speculative fill: p[n,:] = exp(-100). Correct for ~every row; a rare
    // unproven row is recomputed and overwritten after verification.
    const float C = __uint_as_float(CLIP_P_BITS);
    const float4 c4 = make_float4(C, C, C, C);
#pragma unroll
    for (int i = 0; i < 8; i++) __stcs(prow + lane + 32 * i, c4);

    float s = 0.0f;
#pragma unroll
    for (int i = 0; i < 5; i++)
        s += v[i].x * v[i].x + v[i].y * v[i].y + v[i].z * v[i].z + v[i].w * v[i].w;
#pragma unroll
    for (int o = 16; o > 0; o >>= 1) s += __shfl_xor_sync(0xFFFFFFFFu, s, o);

    // Wait for k_pre completion (+ memory visibility). HW wait, not a spin.
    asm volatile("griddepcontrol.wait;" ::: "memory");

    bool clipped = (s > g_th640);
    if (!clipped) {
        // Stage 2: extend to prefix 1024 (3 more float4/lane; ~5% of rows)
        float s2 = 0.0f;
#pragma unroll
        for (int i = 5; i < 8; i++) {
            float4 w4 = __ldcs(xr + lane + 32 * i);
            s2 += w4.x * w4.x + w4.y * w4.y + w4.z * w4.z + w4.w * w4.w;
        }
#pragma unroll
        for (int o = 16; o > 0; o >>= 1) s2 += __shfl_xor_sync(0xFFFFFFFFu, s2, o);
        s += s2;
        clipped = (s > g_th1024);
    }

    if (clipped) {
        if (lane == 0) y[n] = g_yconst;   // speculative p row already correct
    } else {
        // Stage 3: exact fallback for an unproven row (insurance; ~never).
        // Computes full x2, and mu2 inline per h (no precomputed tables).
        // Overwrites are same-lane as the speculative fill (lane owns h with
        // ((h>>2)&31)==lane) => same-thread program order, no race.
        float s3 = 0.0f;
#pragma unroll 1
        for (int i = 8; i < 16; i++) {
            float4 w4 = __ldcs(xr + lane + 32 * i);
            s3 += w4.x * w4.x + w4.y * w4.y + w4.z * w4.z + w4.w * w4.w;
        }
#pragma unroll
        for (int o = 16; o > 0; o >>= 1) s3 += __shfl_xor_sync(0xFFFFFFFFu, s3, o);
        s += s3;   // exact ||x_n||^2

        const float* xs = (const float*)xr;
        float z = 0.0f;
#pragma unroll 1
        for (int h = 0; h < H_; h++) {
            const float* mr = Mu + (size_t)h * D_;
            float dot = 0.0f, m2 = 0.0f;
#pragma unroll 1
            for (int k = lane; k < D_; k += 32) {
                float mv = mr[k];
                dot += xs[k] * mv;
                m2  += mv * mv;
            }
#pragma unroll
            for (int o = 16; o > 0; o >>= 1) {
                dot += __shfl_xor_sync(0xFFFFFFFFu, dot, o);
                m2  += __shfl_xor_sync(0xFFFFFFFFu, m2, o);
            }
            float sd = Sd[h];
            float power = -0.5f * (s - 2.0f * dot + m2) / (sd * sd);
            power = fminf(fmaxf(power, -100.0f), 40.0f);
            float pv = expf(power);
            if (lane == ((h >> 2) & 31)) p[(size_t)n * H_ + h] = pv;
            if (lane == 0) z += pv * W[h];
        }
        if (lane == 0) {
            float tt = mul_rn(2.0f / 3.0f, z);
            float th = (fabsf(tt) < 1e-5f) ? tt : tanhf(tt);
            y[n] = mul_rn(1.7159f, th);
        }
    }
}

extern "C" void kernel_launch(void* const* d_in, const int* in_sizes, int n_in,
                              void* d_out, int out_size) {
    const float* x  = (const float*)d_in[0];
    const float* Mu = (const float*)d_in[1];
    const float* Sd = (const float*)d_in[2];
    const float* W  = (const float*)d_in[3];
    float* y = (float*)d_out;          // first N_ elements
    float* p = (float*)d_out + N_;     // then N_*H_ elements

    k_pre<<<1024, 256>>>(Mu, Sd, W);

    // k_main with Programmatic Dependent Launch: it begins executing while
    // k_pre is still running; it synchronizes in-kernel via griddepcontrol.wait.
    cudaLaunchAttribute attrs[1];
    attrs[0].id = cudaLaunchAttributeProgrammaticStreamSerialization;
    attrs[0].val.programmaticStreamSerializationAllowed = 1;

    cudaLaunchConfig_t cfg = {};
    cfg.gridDim  = dim3(2048, 1, 1);
    cfg.blockDim = dim3(256, 1, 1);
    cfg.dynamicSmemBytes = 0;
    cfg.stream = 0;            // legacy default stream (the captured stream)
    cfg.attrs = attrs;
    cfg.numAttrs = 1;

    cudaLaunchKernelEx(&cfg, k_main, x, Mu, Sd, W, y, p);
}

// round 16
// speedup vs baseline: 1.5541x; 1.0861x over previous
#include <cuda_runtime.h>
#include <math.h>

#define N_ 16384
#define D_ 2048
#define H_ 1024

// fp32(exp(-100)) = 27 * 2^-149 (subnormal), bit pattern 0x0000001B.
#define CLIP_P_BITS 27u

// ---------------- scratch (device globals; no allocation allowed) ----------
__device__ int   g_max640_bits;    // atomicMax of prefix-640 mu norms (>=0)
__device__ int   g_max1024_bits;   // atomicMax of prefix-1024 mu norms (>=0)
__device__ int   g_count;          // last-block-done counter (self-resetting)
__device__ float g_maxsd2;
__device__ float g_yconst;         // y for a clipped row
__device__ float g_th640;          // row clips if prefix-640 x2 > this
__device__ float g_th1024;         // row clips if prefix-1024 x2 > this

// Non-FTZ fp32 ops (immune to any -ftz / fast-math compile flags).
__device__ __forceinline__ float mul_rn(float a, float b) {
    float c; asm("mul.rn.f32 %0, %1, %2;" : "=f"(c) : "f"(a), "f"(b)); return c;
}
__device__ __forceinline__ float add_rn(float a, float b) {
    float c; asm("add.rn.f32 %0, %1, %2;" : "=f"(c) : "f"(a), "f"(b)); return c;
}

// ---------------- K1: prologue (PDL primary) --------------------------------
// 128 blocks x 256 threads; warp per Mu row (8 rows/block), 8 independent
// float4 loads per lane (MLP=8) covering Mu[row, 0:1024]. Fewer primary
// blocks => all signal launch_dependents almost immediately (k_main starts
// sooner); MLP=8 => the 4MB read is bandwidth- not latency-bound, so the
// thresholds publish earlier and k_main's wave-1 waits clear sooner.
__global__ void __launch_bounds__(256) k_pre(const float* __restrict__ Mu,
                                             const float* __restrict__ Sd,
                                             const float* __restrict__ W) {
    asm volatile("griddepcontrol.launch_dependents;" ::: "memory");

    __shared__ float sh[256];
    __shared__ float sh2[256];
    const int t = threadIdx.x;
    const int warp = t >> 5;
    const int lane = t & 31;
    const int row  = blockIdx.x * 8 + warp;

    // 8 independent float4 per lane cover Mu[row, 0:1024]
    const float4* r = (const float4*)(Mu + (size_t)row * D_);
    float4 v[8];
#pragma unroll
    for (int j = 0; j < 8; j++) v[j] = r[lane + 32 * j];

    float sq = 0.0f, sq6 = 0.0f;
#pragma unroll
    for (int j = 0; j < 8; j++) {
        float q = v[j].x * v[j].x + v[j].y * v[j].y
                + v[j].z * v[j].z + v[j].w * v[j].w;
        sq += q;
        if (j < 5) sq6 += q;   // float4 idx < 160 <=> cols < 640
    }
#pragma unroll
    for (int o = 16; o > 0; o >>= 1) {
        sq  += __shfl_xor_sync(0xFFFFFFFFu, sq, o);
        sq6 += __shfl_xor_sync(0xFFFFFFFFu, sq6, o);
    }
    if (lane == 0) {
        atomicMax(&g_max640_bits,  __float_as_int(sq6));
        atomicMax(&g_max1024_bits, __float_as_int(sq));
    }

    if (blockIdx.x == 0) {
        // maxsd2 + exact subnormal z over 1024 (4 per thread)
        float msd = 0.0f;
        const float C = __uint_as_float(CLIP_P_BITS);
        float zp = 0.0f;
#pragma unroll
        for (int i = 0; i < 4; i++) {
            float sd = Sd[t + 256 * i];
            msd = fmaxf(msd, sd * sd);
            // exact: products are multiples of 2^-149, |sum| << 2^-126,
            // so fp32 adds are exact and order-independent.
            zp = add_rn(zp, mul_rn(C, W[t + 256 * i]));
        }
        sh[t] = msd;
        sh2[t] = zp;
        __syncthreads();
        for (int o = 128; o > 0; o >>= 1) {
            if (t < o) {
                sh[t] = fmaxf(sh[t], sh[t + o]);
                sh2[t] = add_rn(sh2[t], sh2[t + o]);
            }
            __syncthreads();
        }
        if (t == 0) {
            g_maxsd2 = sh[0];
            float z = sh2[0];
            float tt = mul_rn(2.0f / 3.0f, z);                // subnormal-safe
            float th = (fabsf(tt) < 1e-5f) ? tt : tanhf(tt);  // tanh(x)==x tiny
            g_yconst = mul_rn(1.7159f, th);
        }
    }
    __syncthreads();

    if (t == 0) {
        __threadfence();
        int c = atomicAdd(&g_count, 1);
        if (c == (int)gridDim.x - 1) {   // last block: publish thresholds
            __threadfence();
            // For any coordinate-prefix S: dist(n,h) >= (||x_S||-||mu_h,S||)^2
            // when ||x_S|| > ||mu_h,S||. Row clips for all h if
            //   ||x_S|| > max_h||mu_h,S|| + sqrt(200*maxsd2*1.001 + 4)
            // (margins cover our fp error AND the reference's GEMM rounding).
            float R = sqrtf(200.0f * g_maxsd2 * 1.001f + 4.0f);
            float a6  = sqrtf(__int_as_float(g_max640_bits))  + R;
            float a10 = sqrtf(__int_as_float(g_max1024_bits)) + R;
            g_th640  = a6 * a6;
            g_th1024 = a10 * a10;
            // reset for next graph replay
            g_max640_bits = 0;
            g_max1024_bits = 0;
            g_count = 0;
            __threadfence();
        }
    }
}

// ---------------- K2: fused main (PDL secondary) — R15 verbatim -------------
// 2048 blocks x 256 threads; warp per x row.
// Stage-1 x loads (prefix 640) and the SPECULATIVE p-row fill (value C is
// input-independent) are issued BEFORE griddepcontrol.wait, hiding k_pre.
// Stage-2 (prefix 1024, ~2% of rows) and stage-3 (exact fallback, ~never)
// run after the wait.
__global__ void __launch_bounds__(256, 5) k_main(const float* __restrict__ x,
                                                 const float* __restrict__ Mu,
                                                 const float* __restrict__ Sd,
                                                 const float* __restrict__ W,
                                                 float* __restrict__ y,
                                                 float* __restrict__ p) {
    const int warp = threadIdx.x >> 5;
    const int lane = threadIdx.x & 31;
    const int n    = blockIdx.x * 8 + warp;
    const float4* xr = (const float4*)(x + (size_t)n * D_);
    float4* prow = (float4*)(p + (size_t)n * H_);

    // Stage 1: lower bound on ||x_n||^2 from the first 640 elems
    // (sums of squares are monotone, so any prefix is a valid lower bound)
    float4 v[5];
#pragma unroll
    for (int i = 0; i < 5; i++) v[i] = xr[lane + 32 * i];

    // Speculative fill: p[n,:] = exp(-100). Correct for ~every row; a rare
    // unproven row is recomputed and overwritten after verification.
    const float C = __uint_as_float(CLIP_P_BITS);
    const float4 c4 = make_float4(C, C, C, C);
#pragma unroll
    for (int i = 0; i < 8; i++) __stcs(prow + lane + 32 * i, c4);

    float s = 0.0f;
#pragma unroll
    for (int i = 0; i < 5; i++)
        s += v[i].x * v[i].x + v[i].y * v[i].y + v[i].z * v[i].z + v[i].w * v[i].w;
#pragma unroll
    for (int o = 16; o > 0; o >>= 1) s += __shfl_xor_sync(0xFFFFFFFFu, s, o);

    // Wait for k_pre completion (+ memory visibility). HW wait, not a spin.
    asm volatile("griddepcontrol.wait;" ::: "memory");

    bool clipped = (s > g_th640);
    if (!clipped) {
        // Stage 2: extend to prefix 1024 (3 more float4/lane; ~2% of rows)
        float s2 = 0.0f;
#pragma unroll
        for (int i = 5; i < 8; i++) {
            float4 w4 = __ldcs(xr + lane + 32 * i);
            s2 += w4.x * w4.x + w4.y * w4.y + w4.z * w4.z + w4.w * w4.w;
        }
#pragma unroll
        for (int o = 16; o > 0; o >>= 1) s2 += __shfl_xor_sync(0xFFFFFFFFu, s2, o);
        s += s2;
        clipped = (s > g_th1024);
    }

    if (clipped) {
        if (lane == 0) y[n] = g_yconst;   // speculative p row already correct
    } else {
        // Stage 3: exact fallback for an unproven row (insurance; ~never).
        // Computes full x2, and mu2 inline per h (no precomputed tables).
        // Overwrites are same-lane as the speculative fill (lane owns h with
        // ((h>>2)&31)==lane) => same-thread program order, no race.
        float s3 = 0.0f;
#pragma unroll 1
        for (int i = 8; i < 16; i++) {
            float4 w4 = __ldcs(xr + lane + 32 * i);
            s3 += w4.x * w4.x + w4.y * w4.y + w4.z * w4.z + w4.w * w4.w;
        }
#pragma unroll
        for (int o = 16; o > 0; o >>= 1) s3 += __shfl_xor_sync(0xFFFFFFFFu, s3, o);
        s += s3;   // exact ||x_n||^2

        const float* xs = (const float*)xr;
        float z = 0.0f;
#pragma unroll 1
        for (int h = 0; h < H_; h++) {
            const float* mr = Mu + (size_t)h * D_;
            float dot = 0.0f, m2 = 0.0f;
#pragma unroll 1
            for (int k = lane; k < D_; k += 32) {
                float mv = mr[k];
                dot += xs[k] * mv;
                m2  += mv * mv;
            }
#pragma unroll
            for (int o = 16; o > 0; o >>= 1) {
                dot += __shfl_xor_sync(0xFFFFFFFFu, dot, o);
                m2  += __shfl_xor_sync(0xFFFFFFFFu, m2, o);
            }
            float sd = Sd[h];
            float power = -0.5f * (s - 2.0f * dot + m2) / (sd * sd);
            power = fminf(fmaxf(power, -100.0f), 40.0f);
            float pv = expf(power);
            if (lane == ((h >> 2) & 31)) p[(size_t)n * H_ + h] = pv;
            if (lane == 0) z += pv * W[h];
        }
        if (lane == 0) {
            float tt = mul_rn(2.0f / 3.0f, z);
            float th = (fabsf(tt) < 1e-5f) ? tt : tanhf(tt);
            y[n] = mul_rn(1.7159f, th);
        }
    }
}

extern "C" void kernel_launch(void* const* d_in, const int* in_sizes, int n_in,
                              void* d_out, int out_size) {
    const float* x  = (const float*)d_in[0];
    const float* Mu = (const float*)d_in[1];
    const float* Sd = (const float*)d_in[2];
    const float* W  = (const float*)d_in[3];
    float* y = (float*)d_out;          // first N_ elements
    float* p = (float*)d_out + N_;     // then N_*H_ elements

    k_pre<<<128, 256>>>(Mu, Sd, W);

    // k_main with Programmatic Dependent Launch: it begins executing while
    // k_pre is still running; it synchronizes in-kernel via griddepcontrol.wait.
    cudaLaunchAttribute attrs[1];
    attrs[0].id = cudaLaunchAttributeProgrammaticStreamSerialization;
    attrs[0].val.programmaticStreamSerializationAllowed = 1;

    cudaLaunchConfig_t cfg = {};
    cfg.gridDim  = dim3(2048, 1, 1);
    cfg.blockDim = dim3(256, 1, 1);
    cfg.dynamicSmemBytes = 0;
    cfg.stream = 0;            // legacy default stream (the captured stream)
    cfg.attrs = attrs;
    cfg.numAttrs = 1;

    cudaLaunchKernelEx(&cfg, k_main, x, Mu, Sd, W, y, p);
}